// round 12
// baseline (speedup 1.0000x reference)
#include <cuda_runtime.h>
#include <cuda_bf16.h>

// Problem shape (fixed per problem instance)
#define B_MAX 16
#define S_DIM 4096
#define D_DIM 512
#define D4 (D_DIM / 4)                       // 128 float4 per row
#define NCHUNK 128                           // strided row-groups per batch
#define THREADS 128                          // one float4 column-slot per thread

// Deterministic partial-sum scratch: [B][NCHUNK][D] floats = 4 MiB (L2-resident)
__device__ float4 g_scratch[B_MAX * NCHUNK * D4];
// Per-batch arrival counters; atomicInc wraps at NCHUNK so every graph replay
// starts from 0 (statically zero-initialized).
__device__ unsigned int g_count[B_MAX];

// xs_len may be int32 (JAX x64-disabled downcast) or int64.
// Little-endian sniff: word[1] is the high half of len[0] if int64 (== 0,
// since len <= 4096), or len[1] if int32 (in [1,4096], != 0).
__device__ __forceinline__ long long read_len(const void* p, int b)
{
    const int* p32 = (const int*)p;
    if (p32[1] == 0) {
        return ((const long long*)p)[b];   // int64 layout
    } else {
        return (long long)p32[b];          // int32 layout
    }
}

// Fused: grid (B, NCHUNK), B fast axis. Chunk c of batch b sums rows
// {c, c+128, c+256, ...} < L (balanced, max 32 rows). The 128th CTA to finish
// for a batch reduces that batch's 128 partials and writes the output row —
// overlapping each batch's finish with other batches' streaming.
__global__ __launch_bounds__(THREADS)
void mean_fused_kernel(const float* __restrict__ xs,
                       const void* __restrict__ xs_len,
                       float* __restrict__ out)
{
    const int b     = blockIdx.x;        // 0..B-1 (fast axis)
    const int chunk = blockIdx.y;        // 0..NCHUNK-1
    const int t     = threadIdx.x;       // 0..127 -> float4 column slot

    const long long L = read_len(xs_len, b);
    // rows r = chunk + k*NCHUNK < L  ->  n = ceil((L - chunk)/NCHUNK), clamped
    long long nll = (L - chunk + NCHUNK - 1) / NCHUNK;
    const int n = nll > 0 ? (int)nll : 0;

    float4 acc = make_float4(0.f, 0.f, 0.f, 0.f);

    if (n > 0) {
        const float4* p = reinterpret_cast<const float4*>(
            xs + (size_t)b * S_DIM * D_DIM + (size_t)chunk * D_DIM) + t;
        const size_t step = (size_t)NCHUNK * D4;   // float4 elems per row-stride

        float4 a0 = make_float4(0.f, 0.f, 0.f, 0.f);
        float4 a1 = make_float4(0.f, 0.f, 0.f, 0.f);
        float4 a2 = make_float4(0.f, 0.f, 0.f, 0.f);
        float4 a3 = make_float4(0.f, 0.f, 0.f, 0.f);

        int k = 0;
        // 8 independent LDG.128 front-batched per iteration -> MLP ~8/thread
        for (; k + 8 <= n; k += 8) {
            const float4* q = p + (size_t)k * step;
            float4 v0 = q[0 * step];
            float4 v1 = q[1 * step];
            float4 v2 = q[2 * step];
            float4 v3 = q[3 * step];
            float4 v4 = q[4 * step];
            float4 v5 = q[5 * step];
            float4 v6 = q[6 * step];
            float4 v7 = q[7 * step];
            a0.x += v0.x; a0.y += v0.y; a0.z += v0.z; a0.w += v0.w;
            a1.x += v1.x; a1.y += v1.y; a1.z += v1.z; a1.w += v1.w;
            a2.x += v2.x; a2.y += v2.y; a2.z += v2.z; a2.w += v2.w;
            a3.x += v3.x; a3.y += v3.y; a3.z += v3.z; a3.w += v3.w;
            a0.x += v4.x; a0.y += v4.y; a0.z += v4.z; a0.w += v4.w;
            a1.x += v5.x; a1.y += v5.y; a1.z += v5.z; a1.w += v5.w;
            a2.x += v6.x; a2.y += v6.y; a2.z += v6.z; a2.w += v6.w;
            a3.x += v7.x; a3.y += v7.y; a3.z += v7.z; a3.w += v7.w;
        }
        for (; k < n; k++) {
            float4 v = p[(size_t)k * step];
            a0.x += v.x; a0.y += v.y; a0.z += v.z; a0.w += v.w;
        }

        acc.x = (a0.x + a1.x) + (a2.x + a3.x);
        acc.y = (a0.y + a1.y) + (a2.y + a3.y);
        acc.z = (a0.z + a1.z) + (a2.z + a3.z);
        acc.w = (a0.w + a1.w) + (a2.w + a3.w);
    }

    g_scratch[((size_t)b * NCHUNK + chunk) * D4 + t] = acc;

    // ---- last-CTA-done handoff for this batch ----
    __threadfence();                 // release: partials visible device-wide
    __shared__ bool am_last;
    __syncthreads();                 // all threads' stores precede the arrive
    if (t == 0) {
        unsigned int prev = atomicInc(&g_count[b], NCHUNK - 1);
        am_last = (prev == NCHUNK - 1);   // wraps to 0 -> ready for next replay
    }
    __syncthreads();

    if (am_last) {
        __threadfence();             // acquire: see all other CTAs' partials

        // Thread t owns output float4 column t. Reads are coalesced per
        // iteration (consecutive t -> contiguous 16B). Fixed ascending chunk
        // order with 8 independent accumulators -> deterministic.
        const float4* src = &g_scratch[(size_t)b * NCHUNK * D4 + t];

        float4 s0 = make_float4(0.f, 0.f, 0.f, 0.f);
        float4 s1 = make_float4(0.f, 0.f, 0.f, 0.f);
        float4 s2 = make_float4(0.f, 0.f, 0.f, 0.f);
        float4 s3 = make_float4(0.f, 0.f, 0.f, 0.f);

        #pragma unroll
        for (int c = 0; c < NCHUNK; c += 8) {
            float4 w0 = src[(c + 0) * D4];
            float4 w1 = src[(c + 1) * D4];
            float4 w2 = src[(c + 2) * D4];
            float4 w3 = src[(c + 3) * D4];
            float4 w4 = src[(c + 4) * D4];
            float4 w5 = src[(c + 5) * D4];
            float4 w6 = src[(c + 6) * D4];
            float4 w7 = src[(c + 7) * D4];
            s0.x += w0.x; s0.y += w0.y; s0.z += w0.z; s0.w += w0.w;
            s1.x += w1.x; s1.y += w1.y; s1.z += w1.z; s1.w += w1.w;
            s2.x += w2.x; s2.y += w2.y; s2.z += w2.z; s2.w += w2.w;
            s3.x += w3.x; s3.y += w3.y; s3.z += w3.z; s3.w += w3.w;
            s0.x += w4.x; s0.y += w4.y; s0.z += w4.z; s0.w += w4.w;
            s1.x += w5.x; s1.y += w5.y; s1.z += w5.z; s1.w += w5.w;
            s2.x += w6.x; s2.y += w6.y; s2.z += w6.z; s2.w += w6.w;
            s3.x += w7.x; s3.y += w7.y; s3.z += w7.z; s3.w += w7.w;
        }

        float4 tot;
        tot.x = (s0.x + s1.x) + (s2.x + s3.x);
        tot.y = (s0.y + s1.y) + (s2.y + s3.y);
        tot.z = (s0.z + s1.z) + (s2.z + s3.z);
        tot.w = (s0.w + s1.w) + (s2.w + s3.w);

        const float inv = 1.0f / (float)L;
        tot.x *= inv; tot.y *= inv; tot.z *= inv; tot.w *= inv;

        reinterpret_cast<float4*>(out + (size_t)b * D_DIM)[t] = tot;
    }
}

extern "C" void kernel_launch(void* const* d_in, const int* in_sizes, int n_in,
                              void* d_out, int out_size)
{
    const float* xs     = (const float*)d_in[0];
    const void*  xs_len = d_in[1];
    float*       out    = (float*)d_out;

    const int B = in_sizes[1];   // number of sequences (16)

    dim3 grid(B, NCHUNK);
    mean_fused_kernel<<<grid, THREADS>>>(xs, xs_len, out);
}

// round 14
// speedup vs baseline: 1.2533x; 1.2533x over previous
#include <cuda_runtime.h>
#include <cuda_bf16.h>

// Problem shape (fixed per problem instance)
#define B_MAX 16
#define S_DIM 4096
#define D_DIM 512
#define D4 (D_DIM / 4)                       // 128 float4 per row
#define NCHUNK 128                           // strided row-groups per batch
#define THREADS 128                          // one float4 column-slot per thread

// Deterministic partial-sum scratch: [B][NCHUNK][D] floats = 4 MiB (L2-resident)
__device__ float4 g_scratch[B_MAX * NCHUNK * D4];

// xs_len may be int32 (JAX x64-disabled downcast) or int64.
// Little-endian sniff: word[1] is the high half of len[0] if int64 (== 0,
// since len <= 4096), or len[1] if int32 (in [1,4096], != 0).
__device__ __forceinline__ long long read_len(const void* p, int b)
{
    const int* p32 = (const int*)p;
    if (p32[1] == 0) {
        return ((const long long*)p)[b];   // int64 layout
    } else {
        return (long long)p32[b];          // int32 layout
    }
}

// Accum: grid (B, NCHUNK). Chunk c of batch b sums rows {c, c+128, ...} < L.
// Balanced (max 32 rows per CTA); batch-fast grid axis mixes batches per SM.
__global__ __launch_bounds__(THREADS)
void mean_accum_kernel(const float* __restrict__ xs,
                       const void* __restrict__ xs_len)
{
    const int b     = blockIdx.x;        // 0..B-1 (fast axis)
    const int chunk = blockIdx.y;        // 0..NCHUNK-1
    const int t     = threadIdx.x;       // 0..127 -> float4 column slot

    const long long L = read_len(xs_len, b);
    long long nll = (L - chunk + NCHUNK - 1) / NCHUNK;
    const int n = nll > 0 ? (int)nll : 0;

    float4* outp = &g_scratch[((size_t)b * NCHUNK + chunk) * D4 + t];

    if (n <= 0) {
        *outp = make_float4(0.f, 0.f, 0.f, 0.f);
        // this CTA is done; allow dependent grid to start scheduling
        asm volatile("griddepcontrol.launch_dependents;");
        return;
    }

    const float4* p = reinterpret_cast<const float4*>(
        xs + (size_t)b * S_DIM * D_DIM + (size_t)chunk * D_DIM) + t;
    const size_t step = (size_t)NCHUNK * D4;   // float4 elements per row-stride

    float4 a0 = make_float4(0.f, 0.f, 0.f, 0.f);
    float4 a1 = make_float4(0.f, 0.f, 0.f, 0.f);
    float4 a2 = make_float4(0.f, 0.f, 0.f, 0.f);
    float4 a3 = make_float4(0.f, 0.f, 0.f, 0.f);

    int k = 0;
    // 8 independent LDG.128 front-batched per iteration -> MLP ~8/thread
    for (; k + 8 <= n; k += 8) {
        const float4* q = p + (size_t)k * step;
        float4 v0 = q[0 * step];
        float4 v1 = q[1 * step];
        float4 v2 = q[2 * step];
        float4 v3 = q[3 * step];
        float4 v4 = q[4 * step];
        float4 v5 = q[5 * step];
        float4 v6 = q[6 * step];
        float4 v7 = q[7 * step];
        a0.x += v0.x; a0.y += v0.y; a0.z += v0.z; a0.w += v0.w;
        a1.x += v1.x; a1.y += v1.y; a1.z += v1.z; a1.w += v1.w;
        a2.x += v2.x; a2.y += v2.y; a2.z += v2.z; a2.w += v2.w;
        a3.x += v3.x; a3.y += v3.y; a3.z += v3.z; a3.w += v3.w;
        a0.x += v4.x; a0.y += v4.y; a0.z += v4.z; a0.w += v4.w;
        a1.x += v5.x; a1.y += v5.y; a1.z += v5.z; a1.w += v5.w;
        a2.x += v6.x; a2.y += v6.y; a2.z += v6.z; a2.w += v6.w;
        a3.x += v7.x; a3.y += v7.y; a3.z += v7.z; a3.w += v7.w;
    }
    for (; k < n; k++) {
        float4 v = p[(size_t)k * step];
        a0.x += v.x; a0.y += v.y; a0.z += v.z; a0.w += v.w;
    }

    float4 acc;
    acc.x = (a0.x + a1.x) + (a2.x + a3.x);
    acc.y = (a0.y + a1.y) + (a2.y + a3.y);
    acc.z = (a0.z + a1.z) + (a2.z + a3.z);
    acc.w = (a0.w + a1.w) + (a2.w + a3.w);

    *outp = acc;

    // Signal PDL: this CTA's work (including the store above, flushed at
    // kernel completion semantics of griddepcontrol.wait downstream) is done.
    asm volatile("griddepcontrol.launch_dependents;");
}

// Finish: grid (32, B) = 512 CTAs, 128 threads.
// Warp w of CTA x owns float4 column (x*4 + w); lane l owns chunks
// {l, l+32, l+64, l+96}. Four LDG.128 per thread from L2-hot scratch,
// fixed-order pairwise combine + shfl butterfly (deterministic).
__global__ __launch_bounds__(THREADS)
void mean_finish_kernel(const void* __restrict__ xs_len,
                        float* __restrict__ out)
{
    const int b    = blockIdx.y;
    const int col  = blockIdx.x * 4 + (threadIdx.x >> 5);  // 0..127
    const int lane = threadIdx.x & 31;

    // Prologue (address math) runs during accum's tail wave under PDL;
    // wait guarantees accum's stores are visible before we read scratch.
    const float4* src = &g_scratch[(size_t)b * NCHUNK * D4 + col];
    const float inv_pre = 1.0f / (float)read_len(xs_len, b);

    asm volatile("griddepcontrol.wait;");

    float4 u0 = src[(lane +  0) * D4];
    float4 u1 = src[(lane + 32) * D4];
    float4 u2 = src[(lane + 64) * D4];
    float4 u3 = src[(lane + 96) * D4];

    float4 v;
    v.x = (u0.x + u1.x) + (u2.x + u3.x);
    v.y = (u0.y + u1.y) + (u2.y + u3.y);
    v.z = (u0.z + u1.z) + (u2.z + u3.z);
    v.w = (u0.w + u1.w) + (u2.w + u3.w);

    #pragma unroll
    for (int off = 16; off > 0; off >>= 1) {
        v.x += __shfl_xor_sync(0xFFFFFFFFu, v.x, off);
        v.y += __shfl_xor_sync(0xFFFFFFFFu, v.y, off);
        v.z += __shfl_xor_sync(0xFFFFFFFFu, v.z, off);
        v.w += __shfl_xor_sync(0xFFFFFFFFu, v.w, off);
    }

    if (lane == 0) {
        v.x *= inv_pre; v.y *= inv_pre; v.z *= inv_pre; v.w *= inv_pre;
        reinterpret_cast<float4*>(out + (size_t)b * D_DIM)[col] = v;
    }
}

extern "C" void kernel_launch(void* const* d_in, const int* in_sizes, int n_in,
                              void* d_out, int out_size)
{
    const float* xs     = (const float*)d_in[0];
    const void*  xs_len = d_in[1];
    float*       out    = (float*)d_out;

    const int B = in_sizes[1];   // number of sequences (16)

    dim3 grid1(B, NCHUNK);
    mean_accum_kernel<<<grid1, THREADS>>>(xs, xs_len);

    // Finish launched as a programmatic dependent: its CTAs schedule while
    // accum's tail is still running; griddepcontrol.wait provides ordering.
    {
        cudaLaunchConfig_t cfg = {};
        cfg.gridDim  = dim3(32, (unsigned)B);
        cfg.blockDim = dim3(THREADS);
        cfg.dynamicSmemBytes = 0;
        cfg.stream = 0;   // legacy default stream (same as <<<>>> above)

        cudaLaunchAttribute attr[1];
        attr[0].id = cudaLaunchAttributeProgrammaticStreamSerialization;
        attr[0].val.programmaticStreamSerializationAllowed = 1;
        cfg.attrs = attr;
        cfg.numAttrs = 1;

        cudaLaunchKernelEx(&cfg, mean_finish_kernel, (const void*)xs_len, out);
    }
}

// round 15
// speedup vs baseline: 1.4076x; 1.1231x over previous
#include <cuda_runtime.h>
#include <cuda_bf16.h>

// Problem shape (fixed per problem instance)
#define B_MAX 16
#define S_DIM 4096
#define D_DIM 512
#define D4 (D_DIM / 4)                       // 128 float4 per row
#define NCHUNK 256                           // strided row-groups per batch
#define THREADS 128                          // one float4 column-slot per thread

// Deterministic partial-sum scratch: [B][NCHUNK][D] floats = 8 MiB (L2-resident)
__device__ float4 g_scratch[B_MAX * NCHUNK * D4];

// xs_len may be int32 (JAX x64-disabled downcast) or int64.
// Little-endian sniff: word[1] is the high half of len[0] if int64 (== 0,
// since len <= 4096), or len[1] if int32 (in [1,4096], != 0).
__device__ __forceinline__ long long read_len(const void* p, int b)
{
    const int* p32 = (const int*)p;
    if (p32[1] == 0) {
        return ((const long long*)p)[b];   // int64 layout
    } else {
        return (long long)p32[b];          // int32 layout
    }
}

// Accum: grid (B, NCHUNK). Chunk c of batch b sums rows {c, c+256, c+512, ...} < L.
// -> every chunk of a batch does ceil(L/256) +- 1 rows (max 16): fine-grained,
// balanced within a batch. Batch is the fast grid axis so adjacent bids are
// different batches -> resident CTAs on an SM mix long and short batches;
// ~2.3 waves of CTAs smooth the tail via work stealing.
__global__ __launch_bounds__(THREADS)
void mean_accum_kernel(const float* __restrict__ xs,
                       const void* __restrict__ xs_len)
{
    const int b     = blockIdx.x;        // 0..B-1 (fast axis)
    const int chunk = blockIdx.y;        // 0..NCHUNK-1
    const int t     = threadIdx.x;       // 0..127 -> float4 column slot

    const long long L = read_len(xs_len, b);
    // rows r = chunk + k*NCHUNK < L  ->  n = ceil((L - chunk)/NCHUNK), clamped
    long long nll = (L - chunk + NCHUNK - 1) / NCHUNK;
    const int n = nll > 0 ? (int)nll : 0;

    float4* outp = &g_scratch[((size_t)b * NCHUNK + chunk) * D4 + t];

    if (n <= 0) {
        *outp = make_float4(0.f, 0.f, 0.f, 0.f);
        return;
    }

    const float4* p = reinterpret_cast<const float4*>(
        xs + (size_t)b * S_DIM * D_DIM + (size_t)chunk * D_DIM) + t;
    const size_t step = (size_t)NCHUNK * D4;   // float4 elements per row-stride

    float4 a0 = make_float4(0.f, 0.f, 0.f, 0.f);
    float4 a1 = make_float4(0.f, 0.f, 0.f, 0.f);
    float4 a2 = make_float4(0.f, 0.f, 0.f, 0.f);
    float4 a3 = make_float4(0.f, 0.f, 0.f, 0.f);

    int k = 0;
    // 8 independent LDG.128 front-batched per iteration -> MLP ~8/thread
    for (; k + 8 <= n; k += 8) {
        const float4* q = p + (size_t)k * step;
        float4 v0 = q[0 * step];
        float4 v1 = q[1 * step];
        float4 v2 = q[2 * step];
        float4 v3 = q[3 * step];
        float4 v4 = q[4 * step];
        float4 v5 = q[5 * step];
        float4 v6 = q[6 * step];
        float4 v7 = q[7 * step];
        a0.x += v0.x; a0.y += v0.y; a0.z += v0.z; a0.w += v0.w;
        a1.x += v1.x; a1.y += v1.y; a1.z += v1.z; a1.w += v1.w;
        a2.x += v2.x; a2.y += v2.y; a2.z += v2.z; a2.w += v2.w;
        a3.x += v3.x; a3.y += v3.y; a3.z += v3.z; a3.w += v3.w;
        a0.x += v4.x; a0.y += v4.y; a0.z += v4.z; a0.w += v4.w;
        a1.x += v5.x; a1.y += v5.y; a1.z += v5.z; a1.w += v5.w;
        a2.x += v6.x; a2.y += v6.y; a2.z += v6.z; a2.w += v6.w;
        a3.x += v7.x; a3.y += v7.y; a3.z += v7.z; a3.w += v7.w;
    }
    for (; k < n; k++) {
        float4 v = p[(size_t)k * step];
        a0.x += v.x; a0.y += v.y; a0.z += v.z; a0.w += v.w;
    }

    float4 acc;
    acc.x = (a0.x + a1.x) + (a2.x + a3.x);
    acc.y = (a0.y + a1.y) + (a2.y + a3.y);
    acc.z = (a0.z + a1.z) + (a2.z + a3.z);
    acc.w = (a0.w + a1.w) + (a2.w + a3.w);

    *outp = acc;
}

// Finish: grid (32, B) = 512 CTAs, 128 threads.
// Warp w of CTA x owns float4 column (x*4 + w); lane l owns chunks
// {l, l+32, ..., l+224}. Eight LDG.128 per thread from L2-hot scratch,
// fixed-order pairwise combine + shfl butterfly (deterministic).
__global__ __launch_bounds__(THREADS)
void mean_finish_kernel(const void* __restrict__ xs_len,
                        float* __restrict__ out)
{
    const int b    = blockIdx.y;
    const int col  = blockIdx.x * 4 + (threadIdx.x >> 5);  // 0..127
    const int lane = threadIdx.x & 31;

    const float4* src = &g_scratch[(size_t)b * NCHUNK * D4 + col];
    float4 u0 = src[(lane +   0) * D4];
    float4 u1 = src[(lane +  32) * D4];
    float4 u2 = src[(lane +  64) * D4];
    float4 u3 = src[(lane +  96) * D4];
    float4 u4 = src[(lane + 128) * D4];
    float4 u5 = src[(lane + 160) * D4];
    float4 u6 = src[(lane + 192) * D4];
    float4 u7 = src[(lane + 224) * D4];

    float4 v;
    v.x = ((u0.x + u1.x) + (u2.x + u3.x)) + ((u4.x + u5.x) + (u6.x + u7.x));
    v.y = ((u0.y + u1.y) + (u2.y + u3.y)) + ((u4.y + u5.y) + (u6.y + u7.y));
    v.z = ((u0.z + u1.z) + (u2.z + u3.z)) + ((u4.z + u5.z) + (u6.z + u7.z));
    v.w = ((u0.w + u1.w) + (u2.w + u3.w)) + ((u4.w + u5.w) + (u6.w + u7.w));

    #pragma unroll
    for (int off = 16; off > 0; off >>= 1) {
        v.x += __shfl_xor_sync(0xFFFFFFFFu, v.x, off);
        v.y += __shfl_xor_sync(0xFFFFFFFFu, v.y, off);
        v.z += __shfl_xor_sync(0xFFFFFFFFu, v.z, off);
        v.w += __shfl_xor_sync(0xFFFFFFFFu, v.w, off);
    }

    if (lane == 0) {
        const float inv = 1.0f / (float)read_len(xs_len, b);
        v.x *= inv; v.y *= inv; v.z *= inv; v.w *= inv;
        reinterpret_cast<float4*>(out + (size_t)b * D_DIM)[col] = v;
    }
}

extern "C" void kernel_launch(void* const* d_in, const int* in_sizes, int n_in,
                              void* d_out, int out_size)
{
    const float* xs     = (const float*)d_in[0];
    const void*  xs_len = d_in[1];
    float*       out    = (float*)d_out;

    const int B = in_sizes[1];   // number of sequences (16)

    dim3 grid1(B, NCHUNK);
    mean_accum_kernel<<<grid1, THREADS>>>(xs, xs_len);

    dim3 grid2(32, B);
    mean_finish_kernel<<<grid2, THREADS>>>(xs_len, out);
}

// round 16
// speedup vs baseline: 1.6617x; 1.1805x over previous
#include <cuda_runtime.h>
#include <cuda_bf16.h>

// Problem shape (fixed per problem instance)
#define B_MAX 16
#define S_DIM 4096
#define D_DIM 512
#define D4 (D_DIM / 4)                       // 128 float4 per row
#define NCHUNK 128                           // strided row-groups per batch
#define THREADS 128                          // one float4 column-slot per thread

// Deterministic partial-sum scratch: [B][NCHUNK][D] floats = 4 MiB (L2-resident)
__device__ float4 g_scratch[B_MAX * NCHUNK * D4];

// xs_len may be int32 (JAX x64-disabled downcast) or int64.
// Little-endian sniff: word[1] is the high half of len[0] if int64 (== 0,
// since len <= 4096), or len[1] if int32 (in [1,4096], != 0).
__device__ __forceinline__ long long read_len(const void* p, int b)
{
    const int* p32 = (const int*)p;
    if (p32[1] == 0) {
        return ((const long long*)p)[b];   // int64 layout
    } else {
        return (long long)p32[b];          // int32 layout
    }
}

// Streaming (evict-first) float4 load: keep the 128MB read-once xs stream
// from thrashing L2, preserving residency for the 4MiB scratch.
__device__ __forceinline__ float4 ldcs4(const float4* p)
{
    return __ldcs(p);
}

// Accum: grid (B, NCHUNK). Chunk c of batch b sums rows {c, c+128, ...} < L.
// -> every chunk of a batch does ceil(L/128) +- 1 rows (max 32): balanced
// within a batch. Batch is the fast grid axis so adjacent bids are different
// batches -> resident CTAs on an SM mix long and short batches. 2048 CTAs
// are fully resident in one wave (~14 CTAs/SM).
__global__ __launch_bounds__(THREADS)
void mean_accum_kernel(const float* __restrict__ xs,
                       const void* __restrict__ xs_len)
{
    const int b     = blockIdx.x;        // 0..B-1 (fast axis)
    const int chunk = blockIdx.y;        // 0..NCHUNK-1
    const int t     = threadIdx.x;       // 0..127 -> float4 column slot

    const long long L = read_len(xs_len, b);
    // rows r = chunk + k*NCHUNK < L  ->  n = ceil((L - chunk)/NCHUNK), clamped
    long long nll = (L - chunk + NCHUNK - 1) / NCHUNK;
    const int n = nll > 0 ? (int)nll : 0;

    float4* outp = &g_scratch[((size_t)b * NCHUNK + chunk) * D4 + t];

    if (n <= 0) {
        *outp = make_float4(0.f, 0.f, 0.f, 0.f);
        return;
    }

    const float4* p = reinterpret_cast<const float4*>(
        xs + (size_t)b * S_DIM * D_DIM + (size_t)chunk * D_DIM) + t;
    const size_t step = (size_t)NCHUNK * D4;   // float4 elements per row-stride

    float4 a0 = make_float4(0.f, 0.f, 0.f, 0.f);
    float4 a1 = make_float4(0.f, 0.f, 0.f, 0.f);
    float4 a2 = make_float4(0.f, 0.f, 0.f, 0.f);
    float4 a3 = make_float4(0.f, 0.f, 0.f, 0.f);

    int k = 0;
    // 8 independent LDG.128 front-batched per iteration -> MLP ~8/thread
    for (; k + 8 <= n; k += 8) {
        const float4* q = p + (size_t)k * step;
        float4 v0 = ldcs4(q + 0 * step);
        float4 v1 = ldcs4(q + 1 * step);
        float4 v2 = ldcs4(q + 2 * step);
        float4 v3 = ldcs4(q + 3 * step);
        float4 v4 = ldcs4(q + 4 * step);
        float4 v5 = ldcs4(q + 5 * step);
        float4 v6 = ldcs4(q + 6 * step);
        float4 v7 = ldcs4(q + 7 * step);
        a0.x += v0.x; a0.y += v0.y; a0.z += v0.z; a0.w += v0.w;
        a1.x += v1.x; a1.y += v1.y; a1.z += v1.z; a1.w += v1.w;
        a2.x += v2.x; a2.y += v2.y; a2.z += v2.z; a2.w += v2.w;
        a3.x += v3.x; a3.y += v3.y; a3.z += v3.z; a3.w += v3.w;
        a0.x += v4.x; a0.y += v4.y; a0.z += v4.z; a0.w += v4.w;
        a1.x += v5.x; a1.y += v5.y; a1.z += v5.z; a1.w += v5.w;
        a2.x += v6.x; a2.y += v6.y; a2.z += v6.z; a2.w += v6.w;
        a3.x += v7.x; a3.y += v7.y; a3.z += v7.z; a3.w += v7.w;
    }
    for (; k < n; k++) {
        float4 v = ldcs4(p + (size_t)k * step);
        a0.x += v.x; a0.y += v.y; a0.z += v.z; a0.w += v.w;
    }

    float4 acc;
    acc.x = (a0.x + a1.x) + (a2.x + a3.x);
    acc.y = (a0.y + a1.y) + (a2.y + a3.y);
    acc.z = (a0.z + a1.z) + (a2.z + a3.z);
    acc.w = (a0.w + a1.w) + (a2.w + a3.w);

    *outp = acc;
}

// Finish: grid (32, B) = 512 CTAs, 128 threads.
// Warp w of CTA x owns float4 column (x*4 + w); lane l owns chunks
// {l, l+32, l+64, l+96}. Four LDG.128 per thread from L2-hot scratch,
// fixed-order pairwise combine + shfl butterfly (deterministic).
__global__ __launch_bounds__(THREADS)
void mean_finish_kernel(const void* __restrict__ xs_len,
                        float* __restrict__ out)
{
    const int b    = blockIdx.y;
    const int col  = blockIdx.x * 4 + (threadIdx.x >> 5);  // 0..127
    const int lane = threadIdx.x & 31;

    const float4* src = &g_scratch[(size_t)b * NCHUNK * D4 + col];
    float4 u0 = src[(lane +  0) * D4];
    float4 u1 = src[(lane + 32) * D4];
    float4 u2 = src[(lane + 64) * D4];
    float4 u3 = src[(lane + 96) * D4];

    float4 v;
    v.x = (u0.x + u1.x) + (u2.x + u3.x);
    v.y = (u0.y + u1.y) + (u2.y + u3.y);
    v.z = (u0.z + u1.z) + (u2.z + u3.z);
    v.w = (u0.w + u1.w) + (u2.w + u3.w);

    #pragma unroll
    for (int off = 16; off > 0; off >>= 1) {
        v.x += __shfl_xor_sync(0xFFFFFFFFu, v.x, off);
        v.y += __shfl_xor_sync(0xFFFFFFFFu, v.y, off);
        v.z += __shfl_xor_sync(0xFFFFFFFFu, v.z, off);
        v.w += __shfl_xor_sync(0xFFFFFFFFu, v.w, off);
    }

    if (lane == 0) {
        const float inv = 1.0f / (float)read_len(xs_len, b);
        v.x *= inv; v.y *= inv; v.z *= inv; v.w *= inv;
        reinterpret_cast<float4*>(out + (size_t)b * D_DIM)[col] = v;
    }
}

extern "C" void kernel_launch(void* const* d_in, const int* in_sizes, int n_in,
                              void* d_out, int out_size)
{
    const float* xs     = (const float*)d_in[0];
    const void*  xs_len = d_in[1];
    float*       out    = (float*)d_out;

    const int B = in_sizes[1];   // number of sequences (16)

    dim3 grid1(B, NCHUNK);
    mean_accum_kernel<<<grid1, THREADS>>>(xs, xs_len);

    dim3 grid2(32, B);
    mean_finish_kernel<<<grid2, THREADS>>>(xs_len, out);
}